// round 3
// baseline (speedup 1.0000x reference)
#include <cuda_runtime.h>
#include <cuda_bf16.h>
#include <math.h>
#include <stdint.h>

// Problem constants
#define BB 512
#define KK 256
#define NN 512
#define CC 6
#define HALF_N 256   // tracks per block (2 blocks per batch)
#define JP (KK/2)    // 128 k-pairs

#define LOG2E_F 1.4426950408889634f
#define LN2_F   0.6931471805599453f
#define LOG2PI_LOG2E 2.6514961294723187  // log2(2*pi)

// ---------------- scratch (static device globals; no allocation) -------------
__device__ double4 g_part[2 * BB];           // {spatial, efs, cnt, lam} per block
__device__ unsigned int g_done = 0;

// ---------------- fast math helpers ------------------------------------------
__device__ __forceinline__ float ex2f(float x) {
    float y; asm("ex2.approx.ftz.f32 %0, %1;" : "=f"(y) : "f"(x)); return y;
}
__device__ __forceinline__ float lg2f(float x) {
    float y; asm("lg2.approx.ftz.f32 %0, %1;" : "=f"(y) : "f"(x)); return y;
}
// packed f32x2 helpers
__device__ __forceinline__ unsigned long long pk2(float lo, float hi) {
    unsigned long long r;
    asm("mov.b64 %0, {%1, %2};" : "=l"(r) : "f"(lo), "f"(hi));
    return r;
}
__device__ __forceinline__ void upk2(unsigned long long v, float& lo, float& hi) {
    asm("mov.b64 {%0, %1}, %2;" : "=f"(lo), "=f"(hi) : "l"(v));
}
__device__ __forceinline__ unsigned long long fma2(unsigned long long a,
                                                   unsigned long long b,
                                                   unsigned long long c) {
    unsigned long long d;
    asm("fma.rn.f32x2 %0, %1, %2, %3;" : "=l"(d) : "l"(a), "l"(b), "l"(c));
    return d;
}
__device__ __forceinline__ unsigned long long add2(unsigned long long a,
                                                   unsigned long long b) {
    unsigned long long d;
    asm("add.rn.f32x2 %0, %1, %2;" : "=l"(d) : "l"(a), "l"(b));
    return d;
}

__device__ __forceinline__ double warpRedD(double v) {
    #pragma unroll
    for (int o = 16; o; o >>= 1) v += __shfl_down_sync(0xffffffffu, v, o);
    return v;
}

// ---------------- main kernel (fully fused) -----------------------------------
__global__ __launch_bounds__(256) void main_kernel(
    const float* __restrict__ pi,
    const float* __restrict__ mu,
    const float* __restrict__ L,
    const float* __restrict__ ef_logits,
    const float* __restrict__ tracks,
    const uint32_t* __restrict__ mask,
    float* __restrict__ out)
{
    const int bid  = blockIdx.x;
    const int b    = bid >> 1;
    const int half = bid & 1;
    const int tid  = threadIdx.x;

    // packed coefficient pairs: spc2[j*3+mm] = {pair(c_{2mm}), pair(c_{2mm+1})}
    __shared__ ulonglong2 spc2[JP * 3];              // 6 KB
    __shared__ unsigned long long uce[CC * JP];      // 6 KB: uce[g*JP+j] = {ce(2j,g), ce(2j+1,g)}
    __shared__ double red[8 * 4];
    __shared__ bool isLast;

    // Lambda contribution: only half 0 accumulates pi (K == blockDim == 256)
    double lam = (half == 0) ? (double)pi[(size_t)b * KK + tid] : 0.0;

    const int n0 = half * HALF_N;
    // prefix-mask property: first inactive => all inactive in this range
    const bool blockActive = (mask[(size_t)b * NN + n0] != 0u);

    double spatial = 0.0, efs = 0.0, cnt = 0.0;

    if (blockActive) {
        // ---- staging: thread tid builds monomial coefficients for k = tid ----
        {
            const int i = b * KK + tid;
            double pv = (double)pi[i];
            double a  = (double)L[i * 4 + 0];
            double bb = (double)L[i * 4 + 2];
            double c  = (double)L[i * 4 + 3];
            double m0 = (double)mu[i * 2 + 0];
            double m1 = (double)mu[i * 2 + 1];

            // base2 = log2(pi) - log2(2pi) - log2(a*c)   (always < 0)
            double base2 = log2(pv) - LOG2PI_LOG2E - log2(a * c);

            const double RQ2 = 0.72134752044448170;  // 0.5 * log2(e)
            double A2  = RQ2 / (a * a);              // A^2
            double Cr2 = RQ2 / (c * c);              // Cr^2
            double BA  = bb / a;
            double P = A2 + Cr2 * BA * BA;
            double Q = Cr2;
            double R = -2.0 * Cr2 * BA;

            float cf[6];
            cf[0] = (float)(base2 - P * m0 * m0 - Q * m1 * m1 - R * m0 * m1);
            cf[1] = (float)(2.0 * P * m0 + R * m1);
            cf[2] = (float)(2.0 * Q * m1 + R * m0);
            cf[3] = (float)(-P);
            cf[4] = (float)(-Q);
            cf[5] = (float)(-R);

            float* fv = (float*)spc2;
            const int j = tid >> 1, lane = tid & 1;
            #pragma unroll
            for (int mm = 0; mm < 3; mm++) {
                fv[(j * 3 + mm) * 4 + 0 + lane] = cf[2 * mm];
                fv[(j * 3 + mm) * 4 + 2 + lane] = cf[2 * mm + 1];
            }

            // CE table: lse(ef_logits) - ef_logits[c], transposed [g][k]
            float e[CC];
            float mx = -INFINITY;
            #pragma unroll
            for (int c2 = 0; c2 < CC; c2++) {
                e[c2] = ef_logits[(size_t)i * CC + c2];
                mx = fmaxf(mx, e[c2]);
            }
            float ssum = 0.f;
            #pragma unroll
            for (int c2 = 0; c2 < CC; c2++) ssum += ex2f((e[c2] - mx) * LOG2E_F);
            float lse = mx + lg2f(ssum) * LN2_F;
            float* fce = (float*)uce;
            #pragma unroll
            for (int c2 = 0; c2 < CC; c2++) fce[c2 * KK + tid] = lse - e[c2];
        }
        __syncthreads();

        // ---- per-track pass: thread tid owns track n0 + tid ----
        const int n = n0 + tid;
        if (mask[(size_t)b * NN + n] != 0u) {
            const float* tr = tracks + ((size_t)b * NN + n) * 6;
            float x0 = tr[0], x1 = tr[1];
            int g = (int)tr[5];

            const unsigned long long x0p  = pk2(x0, x0);
            const unsigned long long x1p  = pk2(x1, x1);
            const unsigned long long xx0p = pk2(x0 * x0, x0 * x0);
            const unsigned long long xx1p = pk2(x1 * x1, x1 * x1);
            const unsigned long long x01p = pk2(x0 * x1, x0 * x1);
            const unsigned long long* cep = uce + g * JP;

            unsigned long long sacc = pk2(0.f, 0.f);
            unsigned long long tacc = sacc;

            #pragma unroll 4
            for (int j = 0; j < JP; j++) {
                ulonglong2 w0 = spc2[j * 3 + 0];  // {c0p, c1p}
                ulonglong2 w1 = spc2[j * 3 + 1];  // {c2p, c3p}
                ulonglong2 w2 = spc2[j * 3 + 2];  // {c4p, c5p}
                unsigned long long q = fma2(w0.y, x0p, w0.x);
                q = fma2(w1.x, x1p, q);
                q = fma2(w1.y, xx0p, q);
                q = fma2(w2.x, xx1p, q);
                q = fma2(w2.y, x01p, q);
                float q1, q2; upk2(q, q1, q2);
                float p1 = ex2f(q1), p2 = ex2f(q2);
                unsigned long long pp = pk2(p1, p2);
                sacc = add2(sacc, pp);
                tacc = fma2(pp, cep[j], tacc);
            }
            float sa, sb, ta, tb;
            upk2(sacc, sa, sb);
            upk2(tacc, ta, tb);
            float s = sa + sb, t = ta + tb;

            spatial = -(double)(lg2f(s) * LN2_F);
            efs     = (double)(t / s);
            cnt     = 1.0;
        }
    }

    // ---- block reduce 4 doubles (uniform control) ----
    spatial = warpRedD(spatial);
    efs     = warpRedD(efs);
    cnt     = warpRedD(cnt);
    lam     = warpRedD(lam);
    const int wid = tid >> 5, lid = tid & 31;
    if (lid == 0) {
        red[wid]      = spatial;
        red[8 + wid]  = efs;
        red[16 + wid] = cnt;
        red[24 + wid] = lam;
    }
    __syncthreads();
    if (tid == 0) {
        double s0 = 0, s1 = 0, s2 = 0, s3 = 0;
        #pragma unroll
        for (int w = 0; w < 8; w++) {
            s0 += red[w]; s1 += red[8 + w]; s2 += red[16 + w]; s3 += red[24 + w];
        }
        g_part[bid] = make_double4(s0, s1, s2, s3);
    }

    // ---- last-block-done finalize (deterministic fixed-order sum) ----
    __threadfence();
    if (tid == 0) {
        unsigned int v = atomicAdd(&g_done, 1u);
        isLast = (v == 2u * BB - 1u);
    }
    __syncthreads();
    if (isLast) {
        double lamSum = 0, cntSum = 0, l1Sum = 0, spSum = 0, efSum = 0;
        for (int b2 = tid; b2 < BB; b2 += 256) {
            double4 e0 = g_part[2 * b2];
            double4 e1 = g_part[2 * b2 + 1];
            double sp  = e0.x + e1.x;
            double ef  = e0.y + e1.y;
            double gc  = e0.z + e1.z;
            double lm  = e0.w + e1.w;
            lamSum += lm;
            cntSum += gc;
            l1Sum  += fabs(lm - gc) * sqrt(gc + 1.0);
            spSum  += sp;
            efSum  += ef;
        }
        lamSum = warpRedD(lamSum);
        cntSum = warpRedD(cntSum);
        l1Sum  = warpRedD(l1Sum);
        spSum  = warpRedD(spSum);
        efSum  = warpRedD(efSum);
        __syncthreads();  // red[] reuse safety
        if (lid == 0) {
            red[wid]      = lamSum;
            red[8 + wid]  = cntSum;
            red[16 + wid] = l1Sum;
            red[24 + wid] = spSum;
        }
        // efSum goes through shuffles only for warp部分; need 5th slot:
        __shared__ double red5[8];
        if (lid == 0) red5[wid] = efSum;
        __syncthreads();
        if (tid == 0) {
            double a0 = 0, a1 = 0, a2 = 0, a3 = 0, a4 = 0;
            #pragma unroll
            for (int w = 0; w < 8; w++) {
                a0 += red[w]; a1 += red[8 + w]; a2 += red[16 + w];
                a3 += red[24 + w]; a4 += red5[w];
            }
            double count_loss = a0 / (double)BB;
            double n_total    = a1 > 1.0 ? a1 : 1.0;
            double count_l1   = a2 / (double)BB;
            double spatialL   = a3 / n_total;
            double efL        = a4 / n_total;
            double total = count_loss + spatialL + efL + count_l1;
            out[0] = (float)total;
            out[1] = (float)spatialL;
            out[2] = (float)count_loss;
            out[3] = (float)count_l1;
            out[4] = (float)efL;
            g_done = 0;  // reset for next graph replay
        }
    }
}

// ---------------- launch -------------------------------------------------------
extern "C" void kernel_launch(void* const* d_in, const int* in_sizes, int n_in,
                              void* d_out, int out_size) {
    const float* pi        = (const float*)d_in[0];
    const float* mu        = (const float*)d_in[1];
    const float* L         = (const float*)d_in[2];
    const float* ef_logits = (const float*)d_in[3];
    const float* tracks    = (const float*)d_in[4];
    const uint32_t* mask   = (const uint32_t*)d_in[5];

    main_kernel<<<2 * BB, 256>>>(pi, mu, L, ef_logits, tracks, mask, (float*)d_out);
}

// round 4
// speedup vs baseline: 1.3692x; 1.3692x over previous
#include <cuda_runtime.h>
#include <cuda_bf16.h>
#include <math.h>
#include <stdint.h>

// Problem constants
#define BB 512
#define KK 256
#define NN 512
#define CC 6
#define HALF_N 256      // tracks per block (2 blocks per batch)
#define TPB 128         // threads per block; each thread owns 2 tracks

#define LOG2E_F 1.4426950408889634f
#define LN2_F   0.6931471805599453f
#define LOG2PI_LOG2E 2.6514961294723187  // log2(2*pi)

// ---------------- scratch (static device globals; no allocation) -------------
__device__ double4 g_part[2 * BB];           // {spatial, efs, cnt, lam} per block
__device__ unsigned int g_done = 0;

// ---------------- fast math helpers ------------------------------------------
__device__ __forceinline__ float ex2f(float x) {
    float y; asm("ex2.approx.ftz.f32 %0, %1;" : "=f"(y) : "f"(x)); return y;
}
__device__ __forceinline__ float lg2f(float x) {
    float y; asm("lg2.approx.ftz.f32 %0, %1;" : "=f"(y) : "f"(x)); return y;
}
__device__ __forceinline__ double warpRedD(double v) {
    #pragma unroll
    for (int o = 16; o; o >>= 1) v += __shfl_down_sync(0xffffffffu, v, o);
    return v;
}

// ---------------- main kernel (fully fused) -----------------------------------
__global__ __launch_bounds__(TPB) void main_kernel(
    const float* __restrict__ pi,
    const float* __restrict__ mu,
    const float* __restrict__ L,
    const float* __restrict__ ef_logits,
    const float* __restrict__ tracks,
    const uint32_t* __restrict__ mask,
    float* __restrict__ out)
{
    const int bid  = blockIdx.x;
    const int b    = bid >> 1;
    const int half = bid & 1;
    const int tid  = threadIdx.x;

    __shared__ float4 scf4[KK];        // {c0,c1,c2,c3}  4 KB
    __shared__ float2 scf2[KK];        // {c4,c5}        2 KB
    __shared__ float  sce[KK * 8];     // ce[k*8+g]      8 KB (pad to 8, bank-clean)
    __shared__ double red[4 * 4];
    __shared__ bool   isLast;

    // Lambda contribution: only half 0 accumulates pi (each thread covers 2 k's)
    double lam = 0.0;
    if (half == 0) {
        lam = (double)pi[(size_t)b * KK + tid] + (double)pi[(size_t)b * KK + tid + TPB];
    }

    const int n0 = half * HALF_N;
    // prefix-mask property: first inactive => whole 256-track range inactive
    const bool blockActive = (mask[(size_t)b * NN + n0] != 0u);

    double spatial = 0.0, efs = 0.0, cnt = 0.0;

    if (blockActive) {
        // ---- staging: thread tid builds coefficients for k = tid, tid+128 ----
        #pragma unroll
        for (int kk = 0; kk < 2; kk++) {
            const int k = tid + kk * TPB;
            const int i = b * KK + k;
            double pv = (double)pi[i];
            double a  = (double)L[i * 4 + 0];
            double bb = (double)L[i * 4 + 2];
            double c  = (double)L[i * 4 + 3];
            double m0 = (double)mu[i * 2 + 0];
            double m1 = (double)mu[i * 2 + 1];

            double base2 = log2(pv) - LOG2PI_LOG2E - log2(a * c);  // < 0

            const double RQ2 = 0.72134752044448170;  // 0.5 * log2(e)
            double A2  = RQ2 / (a * a);
            double Cr2 = RQ2 / (c * c);
            double BA  = bb / a;
            double P = A2 + Cr2 * BA * BA;
            double Q = Cr2;
            double R = -2.0 * Cr2 * BA;

            float4 v4;
            float2 v2;
            v4.x = (float)(base2 - P * m0 * m0 - Q * m1 * m1 - R * m0 * m1);
            v4.y = (float)(2.0 * P * m0 + R * m1);
            v4.z = (float)(2.0 * Q * m1 + R * m0);
            v4.w = (float)(-P);
            v2.x = (float)(-Q);
            v2.y = (float)(-R);
            scf4[k] = v4;
            scf2[k] = v2;

            // CE table: lse(ef_logits) - ef_logits[c]
            float e[CC];
            float mx = -INFINITY;
            #pragma unroll
            for (int c2 = 0; c2 < CC; c2++) {
                e[c2] = ef_logits[(size_t)i * CC + c2];
                mx = fmaxf(mx, e[c2]);
            }
            float ssum = 0.f;
            #pragma unroll
            for (int c2 = 0; c2 < CC; c2++) ssum += ex2f((e[c2] - mx) * LOG2E_F);
            float lse = mx + lg2f(ssum) * LN2_F;
            #pragma unroll
            for (int c2 = 0; c2 < CC; c2++) sce[k * 8 + c2] = lse - e[c2];
        }
        __syncthreads();

        // ---- per-track pass: thread owns tracks n0+tid (A) and n0+tid+128 (B) ----
        const int nA = n0 + tid;
        const int nB = nA + TPB;
        const bool actA = (mask[(size_t)b * NN + nA] != 0u);
        const bool actB = (mask[(size_t)b * NN + nB] != 0u);
        const unsigned balA = __ballot_sync(0xffffffffu, actA);
        const unsigned balB = __ballot_sync(0xffffffffu, actB);
        const bool anyA = (balA != 0u);
        const bool anyB = (balB != 0u);

        if (anyA) {
            // tracks array holds finite data even where masked — safe to compute
            const float* trA = tracks + ((size_t)b * NN + nA) * 6;
            const float* trB = tracks + ((size_t)b * NN + nB) * 6;
            float x0A = trA[0], x1A = trA[1];
            int   gA  = (int)trA[5];
            float xx0A = x0A * x0A, xx1A = x1A * x1A, x01A = x0A * x1A;

            float sA = 0.f, tA = 0.f;

            if (anyB) {
                float x0B = trB[0], x1B = trB[1];
                int   gB  = (int)trB[5];
                float xx0B = x0B * x0B, xx1B = x1B * x1B, x01B = x0B * x1B;
                float sB = 0.f, tB = 0.f;

                #pragma unroll 4
                for (int k = 0; k < KK; k++) {
                    float4 c4 = scf4[k];
                    float2 c2 = scf2[k];
                    float qA = fmaf(c4.y, x0A, c4.x);
                    float qB = fmaf(c4.y, x0B, c4.x);
                    qA = fmaf(c4.z, x1A, qA);
                    qB = fmaf(c4.z, x1B, qB);
                    qA = fmaf(c4.w, xx0A, qA);
                    qB = fmaf(c4.w, xx0B, qB);
                    qA = fmaf(c2.x, xx1A, qA);
                    qB = fmaf(c2.x, xx1B, qB);
                    qA = fmaf(c2.y, x01A, qA);
                    qB = fmaf(c2.y, x01B, qB);
                    float pA = ex2f(qA);
                    float pB = ex2f(qB);
                    sA += pA;
                    sB += pB;
                    tA = fmaf(pA, sce[k * 8 + gA], tA);
                    tB = fmaf(pB, sce[k * 8 + gB], tB);
                }
                if (actB) {
                    spatial -= (double)(lg2f(sB) * LN2_F);
                    efs     += (double)(tB / sB);
                    cnt     += 1.0;
                }
            } else {
                #pragma unroll 4
                for (int k = 0; k < KK; k++) {
                    float4 c4 = scf4[k];
                    float2 c2 = scf2[k];
                    float qA = fmaf(c4.y, x0A, c4.x);
                    qA = fmaf(c4.z, x1A, qA);
                    qA = fmaf(c4.w, xx0A, qA);
                    qA = fmaf(c2.x, xx1A, qA);
                    qA = fmaf(c2.y, x01A, qA);
                    float pA = ex2f(qA);
                    sA += pA;
                    tA = fmaf(pA, sce[k * 8 + gA], tA);
                }
            }
            if (actA) {
                spatial -= (double)(lg2f(sA) * LN2_F);
                efs     += (double)(tA / sA);
                cnt     += 1.0;
            }
        }
    }

    // ---- block reduce 4 doubles (uniform control, 4 warps) ----
    spatial = warpRedD(spatial);
    efs     = warpRedD(efs);
    cnt     = warpRedD(cnt);
    lam     = warpRedD(lam);
    const int wid = tid >> 5, lid = tid & 31;
    if (lid == 0) {
        red[wid]      = spatial;
        red[4 + wid]  = efs;
        red[8 + wid]  = cnt;
        red[12 + wid] = lam;
    }
    __syncthreads();
    if (tid == 0) {
        double s0 = 0, s1 = 0, s2 = 0, s3 = 0;
        #pragma unroll
        for (int w = 0; w < 4; w++) {
            s0 += red[w]; s1 += red[4 + w]; s2 += red[8 + w]; s3 += red[12 + w];
        }
        g_part[bid] = make_double4(s0, s1, s2, s3);
    }

    // ---- last-block-done finalize (deterministic fixed-order sum) ----
    __threadfence();
    if (tid == 0) {
        unsigned int v = atomicAdd(&g_done, 1u);
        isLast = (v == 2u * BB - 1u);
    }
    __syncthreads();
    if (isLast) {
        double lamSum = 0, cntSum = 0, l1Sum = 0, spSum = 0, efSum = 0;
        for (int b2 = tid; b2 < BB; b2 += TPB) {
            double4 e0 = g_part[2 * b2];
            double4 e1 = g_part[2 * b2 + 1];
            double sp = e0.x + e1.x;
            double ef = e0.y + e1.y;
            double gc = e0.z + e1.z;
            double lm = e0.w + e1.w;
            lamSum += lm;
            cntSum += gc;
            l1Sum  += fabs(lm - gc) * sqrt(gc + 1.0);
            spSum  += sp;
            efSum  += ef;
        }
        lamSum = warpRedD(lamSum);
        cntSum = warpRedD(cntSum);
        l1Sum  = warpRedD(l1Sum);
        spSum  = warpRedD(spSum);
        efSum  = warpRedD(efSum);
        __syncthreads();
        __shared__ double red5[4 * 5];
        if (lid == 0) {
            red5[wid]      = lamSum;
            red5[4 + wid]  = cntSum;
            red5[8 + wid]  = l1Sum;
            red5[12 + wid] = spSum;
            red5[16 + wid] = efSum;
        }
        __syncthreads();
        if (tid == 0) {
            double a0 = 0, a1 = 0, a2 = 0, a3 = 0, a4 = 0;
            #pragma unroll
            for (int w = 0; w < 4; w++) {
                a0 += red5[w]; a1 += red5[4 + w]; a2 += red5[8 + w];
                a3 += red5[12 + w]; a4 += red5[16 + w];
            }
            double count_loss = a0 / (double)BB;
            double n_total    = a1 > 1.0 ? a1 : 1.0;
            double count_l1   = a2 / (double)BB;
            double spatialL   = a3 / n_total;
            double efL        = a4 / n_total;
            double total = count_loss + spatialL + efL + count_l1;
            out[0] = (float)total;
            out[1] = (float)spatialL;
            out[2] = (float)count_loss;
            out[3] = (float)count_l1;
            out[4] = (float)efL;
            g_done = 0;  // reset for next graph replay
        }
    }
}

// ---------------- launch -------------------------------------------------------
extern "C" void kernel_launch(void* const* d_in, const int* in_sizes, int n_in,
                              void* d_out, int out_size) {
    const float* pi        = (const float*)d_in[0];
    const float* mu        = (const float*)d_in[1];
    const float* L         = (const float*)d_in[2];
    const float* ef_logits = (const float*)d_in[3];
    const float* tracks    = (const float*)d_in[4];
    const uint32_t* mask   = (const uint32_t*)d_in[5];

    main_kernel<<<2 * BB, TPB>>>(pi, mu, L, ef_logits, tracks, mask, (float*)d_out);
}